// round 4
// baseline (speedup 1.0000x reference)
#include <cuda_runtime.h>
#include <cstdint>
#include <math.h>

#define BB 8
#define LL 2048
#define DD 256

// Scratch (__device__ globals)
__device__ __align__(16) float g_Q[BB*LL*DD];     // rounded Q+bias, permuted-k
__device__ __align__(16) float g_K[BB*LL*DD];     // rounded K+bias, permuted-k
__device__ __align__(16) float g_V[BB*LL*DD];     // rounded V+bias, normal
__device__ __align__(16) float g_VT[BB*DD*LL];    // V transposed [d][k], permuted-k
__device__ __align__(16) float g_colsum[BB*LL];   // colsum -> inverted in place

__device__ __forceinline__ uint32_t f2tf32(float x){
  uint32_t u; asm("cvt.rna.tf32.f32 %0, %1;" : "=r"(u) : "f"(x)); return u;
}
__device__ __forceinline__ float rndf(float x){ return __uint_as_float(f2tf32(x)); }

__device__ __forceinline__ void cp16(uint32_t dst, const void* src){
  asm volatile("cp.async.cg.shared.global [%0], [%1], 16;\n" :: "r"(dst), "l"(src));
}
__device__ __forceinline__ void cpcommit(){ asm volatile("cp.async.commit_group;\n"); }
template<int N> __device__ __forceinline__ void cpwait(){
  asm volatile("cp.async.wait_group %0;\n" :: "n"(N));
}

#define MMA(a0,a1,a2,a3,b0,b1,c) \
  asm volatile("mma.sync.aligned.m16n8k8.row.col.f32.tf32.tf32.f32 " \
    "{%0,%1,%2,%3}, {%4,%5,%6,%7}, {%8,%9}, {%0,%1,%2,%3};" \
    : "+f"(c[0]),"+f"(c[1]),"+f"(c[2]),"+f"(c[3]) \
    : "r"(a0),"r"(a1),"r"(a2),"r"(a3),"r"(b0),"r"(b1))

// permuted position of k-index j within its 8-group: [0,4,1,5,2,6,3,7]
__device__ __forceinline__ int permp(int j){ return (((j)&3)<<1) | ((j)>>2); }

// ============================================================
// Fused QKV GEMM. M=16384 (B*L), N=768 (Q|K|V), K=256.
// BM=128, BN=128, BK=32, 2-stage cp.async, register tf32 cvt.
// grid (6,128): bn0/256 selects section.
// ============================================================
__global__ __launch_bounds__(256,2) void qkv_gemm(
    const float* __restrict__ x,
    const float* __restrict__ Wq, const float* __restrict__ bq,
    const float* __restrict__ Wk, const float* __restrict__ bk,
    const float* __restrict__ Wv, const float* __restrict__ bv,
    float* __restrict__ sp)
{
  extern __shared__ uint32_t sm[];
  const int bm0 = blockIdx.y * 128;
  const int bn0 = blockIdx.x * 128;
  const int sec = bn0 >> 8;              // 0=Q, 1=K, 2=V
  const int n_off = bn0 & 255;
  const float* W    = (sec==0) ? Wq : (sec==1) ? Wk : Wv;
  const float* bias = (sec==0) ? bq : (sec==1) ? bk : bv;

  const int tid = threadIdx.x;
  const int warp = tid >> 5, lane = tid & 31;
  const int g = lane >> 2, t = lane & 3;
  const int wm0 = (warp >> 2) * 64;
  const int wn0 = (warp & 3) * 32;
  const uint32_t sb = (uint32_t)__cvta_generic_to_shared(sm);
  const int lr = tid >> 3, lc = (tid & 7) * 4;

  float acc[4][4][4];
  #pragma unroll
  for (int i=0;i<4;i++)
    #pragma unroll
    for (int j=0;j<4;j++)
      #pragma unroll
      for (int f=0;f<4;f++) acc[i][j][f]=0.f;

  #define QKV_LOAD(kt, stg) { \
    _Pragma("unroll") \
    for (int i=0;i<4;i++){ \
      int r = lr + i*32; \
      cp16(sb + (((stg)*4608 + r*36 + lc)<<2), x + (size_t)(bm0+r)*DD + (kt)*32 + lc); \
    } \
    _Pragma("unroll") \
    for (int i=0;i<4;i++){ \
      int r = lr + i*32; \
      cp16(sb + ((9216 + (stg)*4608 + r*36 + lc)<<2), W + (size_t)(n_off+r)*DD + (kt)*32 + lc); \
    } \
  }

  QKV_LOAD(0,0); cpcommit();
  for (int kt = 0; kt < 8; kt++){
    const int stg = kt & 1;
    if (kt+1 < 8){ QKV_LOAD(kt+1, stg^1); cpcommit(); cpwait<1>(); }
    else cpwait<0>();
    __syncthreads();

    const uint32_t* As_ = sm + stg*4608;
    const uint32_t* Bs_ = sm + 9216 + stg*4608;
    #pragma unroll
    for (int ks=0; ks<4; ks++){
      const int k0 = ks*8;
      uint32_t af[4][4], bf[4][2];
      #pragma unroll
      for (int mi=0;mi<4;mi++){
        int r = wm0 + mi*16;
        af[mi][0]=f2tf32(__uint_as_float(As_[(r+g  )*36+k0+t]));
        af[mi][1]=f2tf32(__uint_as_float(As_[(r+g+8)*36+k0+t]));
        af[mi][2]=f2tf32(__uint_as_float(As_[(r+g  )*36+k0+t+4]));
        af[mi][3]=f2tf32(__uint_as_float(As_[(r+g+8)*36+k0+t+4]));
      }
      #pragma unroll
      for (int ni=0;ni<4;ni++){
        int c = wn0 + ni*8;
        bf[ni][0]=f2tf32(__uint_as_float(Bs_[(c+g)*36+k0+t]));
        bf[ni][1]=f2tf32(__uint_as_float(Bs_[(c+g)*36+k0+t+4]));
      }
      #pragma unroll
      for (int mi=0;mi<4;mi++)
        #pragma unroll
        for (int ni=0;ni<4;ni++)
          MMA(af[mi][0],af[mi][1],af[mi][2],af[mi][3],bf[ni][0],bf[ni][1],acc[mi][ni]);
    }
    __syncthreads();
  }
  #undef QKV_LOAD

  // permuted destination columns for this thread's (c, c+1) pair
  const int j0 = 2*t, j1 = 2*t+1;
  const int p0 = permp(j0), p1 = permp(j1);

  #pragma unroll
  for (int mi=0;mi<4;mi++){
    #pragma unroll
    for (int ni=0;ni<4;ni++){
      int r0 = bm0 + wm0 + mi*16 + g;
      int cg = wn0 + ni*8;          // 8-group base
      int c  = n_off + cg + 2*t;    // within-section column
      float2 b2 = *(const float2*)(bias + c);
      float v0=acc[mi][ni][0]+b2.x, v1=acc[mi][ni][1]+b2.y;
      float v2=acc[mi][ni][2]+b2.x, v3=acc[mi][ni][3]+b2.y;
      int r1 = r0 + 8;
      if (sec == 0){
        // sp (unrounded, normal layout)
        int b0=r0>>11, m0=r0&2047, b1=r1>>11, m1=r1&2047;
        *(float2*)(sp + (size_t)b0*(2LL*LL*DD) + (size_t)m0*DD + c) = make_float2(v0,v1);
        *(float2*)(sp + (size_t)b1*(2LL*LL*DD) + (size_t)m1*DD + c) = make_float2(v2,v3);
        // g_Q rounded, permuted
        int base = n_off + cg;
        g_Q[(size_t)r0*DD + base + p0] = rndf(v0);
        g_Q[(size_t)r0*DD + base + p1] = rndf(v1);
        g_Q[(size_t)r1*DD + base + p0] = rndf(v2);
        g_Q[(size_t)r1*DD + base + p1] = rndf(v3);
      } else if (sec == 1){
        int base = n_off + cg;
        g_K[(size_t)r0*DD + base + p0] = rndf(v0);
        g_K[(size_t)r0*DD + base + p1] = rndf(v1);
        g_K[(size_t)r1*DD + base + p0] = rndf(v2);
        g_K[(size_t)r1*DD + base + p1] = rndf(v3);
      } else {
        *(float2*)(g_V + (size_t)r0*DD + c) = make_float2(rndf(v0),rndf(v1));
        *(float2*)(g_V + (size_t)r1*DD + c) = make_float2(rndf(v2),rndf(v3));
      }
    }
  }
}

// ============================================================
// V transpose: g_V [b][k][d] -> g_VT [b][d][perm(k)]
// ============================================================
__global__ void vt_kernel(){
  __shared__ float smt[32][33];
  const int b = blockIdx.z;
  const int k0 = blockIdx.x * 32;
  const int d0 = blockIdx.y * 32;
  const int tx = threadIdx.x, ty = threadIdx.y;  // (32, 8)
  const float* V = g_V + (size_t)b*LL*DD;
  float* VT = g_VT + (size_t)b*DD*LL;
  #pragma unroll
  for (int i=0;i<4;i++)
    smt[ty+8*i][tx] = V[(size_t)(k0+ty+8*i)*DD + d0 + tx];
  __syncthreads();
  // stored col p=tx holds orig k-in-group: (p>>1)&3 then +4 if odd, preserving 8-group
  const int jorig = (((tx&7)>>1)) + ((tx&1)<<2) + (tx & ~7);
  #pragma unroll
  for (int i=0;i<4;i++)
    VT[(size_t)(d0+ty+8*i)*LL + k0 + tx] = smt[jorig][ty+8*i];
}

__global__ void invcs_kernel(){
  int i = blockIdx.x*256 + threadIdx.x;
  g_colsum[i] = 1.0f / g_colsum[i];
}
__global__ void zerocs_kernel(){
  int i = blockIdx.x*256 + threadIdx.x;
  g_colsum[i] = 0.f;
}

// ============================================================
// P-GEMM: P = exp(Q K^T / 16) (+ fused colsum). Q,K permuted-k.
// BM=BN=128, BK=32, 2-stage cp.async, LDS.64 fragment loads.
// ============================================================
__global__ __launch_bounds__(256,2) void pexp_gemm(float* __restrict__ Pout)
{
  extern __shared__ uint32_t sm[];
  const int z = blockIdx.z;
  const float* A = g_Q + (size_t)z*LL*DD;
  const float* B = g_K + (size_t)z*LL*DD;
  float* C = Pout + (size_t)z*LL*LL;

  const int bm0 = blockIdx.y * 128;
  const int bn0 = blockIdx.x * 128;
  const int tid = threadIdx.x;
  const int warp = tid >> 5, lane = tid & 31;
  const int g = lane >> 2, t = lane & 3;
  const int wm0 = (warp >> 2) * 64;
  const int wn0 = (warp & 3) * 32;
  const uint32_t sb = (uint32_t)__cvta_generic_to_shared(sm);
  const int lr = tid >> 3, lc = (tid & 7) * 4;

  float acc[4][4][4];
  #pragma unroll
  for (int i=0;i<4;i++)
    #pragma unroll
    for (int j=0;j<4;j++)
      #pragma unroll
      for (int f=0;f<4;f++) acc[i][j][f]=0.f;

  #define P_LOAD(kt, stg) { \
    _Pragma("unroll") \
    for (int i=0;i<4;i++){ \
      int r = lr + i*32; \
      cp16(sb + (((stg)*4608 + r*36 + lc)<<2), A + (size_t)(bm0+r)*DD + (kt)*32 + lc); \
    } \
    _Pragma("unroll") \
    for (int i=0;i<4;i++){ \
      int r = lr + i*32; \
      cp16(sb + ((9216 + (stg)*4608 + r*36 + lc)<<2), B + (size_t)(bn0+r)*DD + (kt)*32 + lc); \
    } \
  }

  P_LOAD(0,0); cpcommit();
  for (int kt = 0; kt < 8; kt++){
    const int stg = kt & 1;
    if (kt+1 < 8){ P_LOAD(kt+1, stg^1); cpcommit(); cpwait<1>(); }
    else cpwait<0>();
    __syncthreads();

    const uint32_t* As_ = sm + stg*4608;
    const uint32_t* Bs_ = sm + 9216 + stg*4608;
    #pragma unroll
    for (int ks=0; ks<4; ks++){
      const int k0 = ks*8;
      uint32_t af[4][4], bf[4][2];
      #pragma unroll
      for (int mi=0;mi<4;mi++){
        int r = wm0 + mi*16;
        uint2 lo = *(const uint2*)&As_[(r+g  )*36 + k0 + 2*t];
        uint2 hi = *(const uint2*)&As_[(r+g+8)*36 + k0 + 2*t];
        af[mi][0]=lo.x; af[mi][1]=hi.x; af[mi][2]=lo.y; af[mi][3]=hi.y;
      }
      #pragma unroll
      for (int ni=0;ni<4;ni++){
        int c = wn0 + ni*8;
        uint2 bb = *(const uint2*)&Bs_[(c+g)*36 + k0 + 2*t];
        bf[ni][0]=bb.x; bf[ni][1]=bb.y;
      }
      #pragma unroll
      for (int mi=0;mi<4;mi++)
        #pragma unroll
        for (int ni=0;ni<4;ni++)
          MMA(af[mi][0],af[mi][1],af[mi][2],af[mi][3],bf[ni][0],bf[ni][1],acc[mi][ni]);
    }
    __syncthreads();
  }
  #undef P_LOAD

  // epilogue: exp + colsum
  float csum[4][2];
  for (int ni=0;ni<4;ni++){ csum[ni][0]=0.f; csum[ni][1]=0.f; }

  #pragma unroll
  for (int mi=0;mi<4;mi++){
    #pragma unroll
    for (int ni=0;ni<4;ni++){
      int r0 = bm0 + wm0 + mi*16 + g;
      int c  = bn0 + wn0 + ni*8 + 2*t;
      float e0=__expf(acc[mi][ni][0]*0.0625f), e1=__expf(acc[mi][ni][1]*0.0625f);
      float e2=__expf(acc[mi][ni][2]*0.0625f), e3=__expf(acc[mi][ni][3]*0.0625f);
      *(float2*)(C + (size_t)r0*LL + c)     = make_float2(e0,e1);
      *(float2*)(C + (size_t)(r0+8)*LL + c) = make_float2(e2,e3);
      csum[ni][0] += e0+e2; csum[ni][1] += e1+e3;
    }
  }
  float* sCol = (float*)sm;
  __syncthreads();
  if (tid < 128) sCol[tid] = 0.f;
  __syncthreads();
  #pragma unroll
  for (int ni=0;ni<4;ni++){
    atomicAdd(&sCol[wn0 + ni*8 + 2*t    ], csum[ni][0]);
    atomicAdd(&sCol[wn0 + ni*8 + 2*t + 1], csum[ni][1]);
  }
  __syncthreads();
  if (tid < 128) atomicAdd(&g_colsum[z*LL + bn0 + tid], sCol[tid]);
}

// ============================================================
// AV GEMM: C = (P/colsum) @ V, normalized A written back in place.
// BM=64, BN=256, BK=32. A: LDG+scale+STG+cvt (normal layout).
// B: cp.async of g_VT (permuted) -> LDS.64 fragment loads.
// dyn smem: As 2*64*36 + Bs 2*256*36 u32 = 92160 B
// ============================================================
__global__ __launch_bounds__(256,2) void gemm_av(
    float* __restrict__ P, float* __restrict__ Cg)
{
  extern __shared__ uint32_t sm[];
  const int z = blockIdx.z;
  float* A = P + (size_t)z*LL*LL;
  const float* B = g_VT + (size_t)z*DD*LL;
  float* C = Cg + (size_t)z*(2LL*LL*DD);
  const float* inv = g_colsum + z*LL;

  const int bm0 = blockIdx.y * 64;
  const int tid = threadIdx.x;
  const int warp = tid >> 5, lane = tid & 31;
  const int g = lane >> 2, t = lane & 3;
  const int wm0 = (warp >> 2) * 32;
  const int wn0 = (warp & 3) * 64;
  const uint32_t sb = (uint32_t)__cvta_generic_to_shared(sm);
  const int lr = tid >> 3, lc = (tid & 7) * 4;

  float acc[2][8][4];
  #pragma unroll
  for (int i=0;i<2;i++)
    #pragma unroll
    for (int j=0;j<8;j++)
      #pragma unroll
      for (int f=0;f<4;f++) acc[i][j][f]=0.f;

  uint32_t areg[8];

  #define PROC_A(kt) { \
    float4 iv = *(const float4*)(inv + (kt)*32 + lc); \
    _Pragma("unroll") \
    for (int i=0;i<2;i++){ \
      float* ap = A + (size_t)(bm0 + lr + i*32)*LL + (kt)*32 + lc; \
      float4 p = *(const float4*)ap; \
      p.x*=iv.x; p.y*=iv.y; p.z*=iv.z; p.w*=iv.w; \
      *(float4*)ap = p; \
      areg[i*4+0]=f2tf32(p.x); areg[i*4+1]=f2tf32(p.y); \
      areg[i*4+2]=f2tf32(p.z); areg[i*4+3]=f2tf32(p.w); \
    } \
  }
  // B tile: 256 d-rows x 32 k (permuted) from VT
  #define LOAD_B(kt, stg) { \
    _Pragma("unroll") \
    for (int i=0;i<8;i++){ \
      int s = tid + i*256; int d = s>>3; int ch=(s&7)*4; \
      cp16(sb + ((4608 + (stg)*9216 + d*36 + ch)<<2), B + (size_t)d*LL + (kt)*32 + ch); \
    } \
  }

  PROC_A(0);
  LOAD_B(0,0); cpcommit();

  const int nk = LL/32;   // 64
  for (int kt = 0; kt < nk; kt++){
    const int stg = kt & 1;
    #pragma unroll
    for (int i=0;i<2;i++){
      uint32_t* d = sm + stg*2304 + (lr + i*32)*36 + lc;
      *(uint4*)d = make_uint4(areg[i*4],areg[i*4+1],areg[i*4+2],areg[i*4+3]);
    }
    const bool more = (kt + 1 < nk);
    float4 rawp[2]; float4 iv;
    if (more){
      LOAD_B(kt+1, stg^1); cpcommit();
      iv = *(const float4*)(inv + (kt+1)*32 + lc);
      #pragma unroll
      for (int i=0;i<2;i++)
        rawp[i] = *(const float4*)(A + (size_t)(bm0 + lr + i*32)*LL + (kt+1)*32 + lc);
      cpwait<1>();
    } else {
      cpwait<0>();
    }
    __syncthreads();

    const uint32_t* As_ = sm + stg*2304;
    const uint32_t* Bs_ = sm + 4608 + stg*9216;
    #pragma unroll
    for (int ks=0; ks<4; ks++){
      const int k0 = ks*8;
      uint32_t af[2][4], bf[8][2];
      #pragma unroll
      for (int mi=0;mi<2;mi++){
        int r = wm0 + mi*16;
        af[mi][0]=As_[(r+g  )*36+k0+t];   af[mi][1]=As_[(r+g+8)*36+k0+t];
        af[mi][2]=As_[(r+g  )*36+k0+t+4]; af[mi][3]=As_[(r+g+8)*36+k0+t+4];
      }
      #pragma unroll
      for (int ni=0;ni<8;ni++){
        int c = wn0 + ni*8;
        uint2 bb = *(const uint2*)&Bs_[(c+g)*36 + k0 + 2*t];
        bf[ni][0]=bb.x; bf[ni][1]=bb.y;
      }
      #pragma unroll
      for (int mi=0;mi<2;mi++)
        #pragma unroll
        for (int ni=0;ni<8;ni++)
          MMA(af[mi][0],af[mi][1],af[mi][2],af[mi][3],bf[ni][0],bf[ni][1],acc[mi][ni]);
    }

    if (more){
      #pragma unroll
      for (int i=0;i<2;i++){
        float4 p = rawp[i];
        p.x*=iv.x; p.y*=iv.y; p.z*=iv.z; p.w*=iv.w;
        *(float4*)(A + (size_t)(bm0 + lr + i*32)*LL + (kt+1)*32 + lc) = p;
        areg[i*4+0]=f2tf32(p.x); areg[i*4+1]=f2tf32(p.y);
        areg[i*4+2]=f2tf32(p.z); areg[i*4+3]=f2tf32(p.w);
      }
    }
    __syncthreads();
  }
  #undef PROC_A
  #undef LOAD_B

  #pragma unroll
  for (int mi=0;mi<2;mi++){
    #pragma unroll
    for (int ni=0;ni<8;ni++){
      int r = bm0 + wm0 + mi*16 + g;
      int c = wn0 + ni*8 + 2*t;
      *(float2*)(C + (size_t)r*DD + c)     = make_float2(acc[mi][ni][0],acc[mi][ni][1]);
      *(float2*)(C + (size_t)(r+8)*DD + c) = make_float2(acc[mi][ni][2],acc[mi][ni][3]);
    }
  }
}

// ============================================================
extern "C" void kernel_launch(void* const* d_in, const int* in_sizes, int n_in,
                              void* d_out, int out_size)
{
  const float* x  = (const float*)d_in[0];
  const float* Wq = (const float*)d_in[1];
  const float* bq = (const float*)d_in[2];
  const float* Wk = (const float*)d_in[3];
  const float* bk = (const float*)d_in[4];
  const float* Wv = (const float*)d_in[5];
  const float* bv = (const float*)d_in[6];

  float* sp   = (float*)d_out;                  // S_p [B, 2L, D]
  float* Aout = sp + (size_t)BB*2*LL*DD;        // A   [B, L, L]

  const int SM128 = 73728, SMAV = 92160;
  cudaFuncSetAttribute(qkv_gemm,  cudaFuncAttributeMaxDynamicSharedMemorySize, SM128);
  cudaFuncSetAttribute(pexp_gemm, cudaFuncAttributeMaxDynamicSharedMemorySize, SM128);
  cudaFuncSetAttribute(gemm_av,   cudaFuncAttributeMaxDynamicSharedMemorySize, SMAV);

  zerocs_kernel<<<BB*LL/256, 256>>>();

  // Fused QKV projection
  qkv_gemm<<<dim3(6,128,1), 256, SM128>>>(x, Wq, bq, Wk, bk, Wv, bv, sp);

  // V -> VT (transposed, permuted-k)
  vt_kernel<<<dim3(LL/32, DD/32, BB), dim3(32,8)>>>();

  // P = exp(Q K^T / 16) + fused column sums
  pexp_gemm<<<dim3(16,16,BB), 256, SM128>>>(Aout);

  invcs_kernel<<<BB*LL/256, 256>>>();

  // C = (P/colsum) @ V with fused in-place normalization of A
  gemm_av<<<dim3(1,32,BB), 256, SMAV>>>(Aout, sp + (size_t)LL*DD);
}

// round 5
// speedup vs baseline: 1.0859x; 1.0859x over previous
#include <cuda_runtime.h>
#include <cstdint>
#include <math.h>

#define BB 8
#define LL 2048
#define DD 256

// Scratch (__device__ globals)
__device__ __align__(16) float g_Q[BB*LL*DD];     // rounded Q+bias
__device__ __align__(16) float g_K[BB*LL*DD];     // rounded K+bias
__device__ __align__(16) float g_V[BB*LL*DD];     // rounded V+bias
__device__ __align__(16) float g_colsum[BB*LL];   // colsum -> inverted in place

__device__ __forceinline__ uint32_t f2tf32(float x){
  uint32_t u; asm("cvt.rna.tf32.f32 %0, %1;" : "=r"(u) : "f"(x)); return u;
}
__device__ __forceinline__ float rndf(float x){ return __uint_as_float(f2tf32(x)); }

__device__ __forceinline__ void cp16(uint32_t dst, const void* src){
  asm volatile("cp.async.cg.shared.global [%0], [%1], 16;\n" :: "r"(dst), "l"(src));
}
__device__ __forceinline__ void cpcommit(){ asm volatile("cp.async.commit_group;\n"); }
template<int N> __device__ __forceinline__ void cpwait(){
  asm volatile("cp.async.wait_group %0;\n" :: "n"(N));
}

#define MMA(a0,a1,a2,a3,b0,b1,c) \
  asm volatile("mma.sync.aligned.m16n8k8.row.col.f32.tf32.tf32.f32 " \
    "{%0,%1,%2,%3}, {%4,%5,%6,%7}, {%8,%9}, {%0,%1,%2,%3};" \
    : "+f"(c[0]),"+f"(c[1]),"+f"(c[2]),"+f"(c[3]) \
    : "r"(a0),"r"(a1),"r"(a2),"r"(a3),"r"(b0),"r"(b1))

__global__ void invcs_kernel(){
  int i = blockIdx.x*256 + threadIdx.x;
  g_colsum[i] = 1.0f / g_colsum[i];
}
__global__ void zerocs_kernel(){
  int i = blockIdx.x*256 + threadIdx.x;
  g_colsum[i] = 0.f;
}

// ============================================================
// Fused QKV GEMM. M=16384 (B*L), N=768 (Q|K|V), K=256.
// CTA 128x128, 128 threads, 4 warps of 64x64. cvt-in-register.
// dyn smem: 2*(128+128)*36*4 = 73728 B
// ============================================================
__global__ __launch_bounds__(128,2) void qkv_gemm(
    const float* __restrict__ x,
    const float* __restrict__ Wq, const float* __restrict__ bq,
    const float* __restrict__ Wk, const float* __restrict__ bk,
    const float* __restrict__ Wv, const float* __restrict__ bv,
    float* __restrict__ sp)
{
  extern __shared__ uint32_t sm[];
  const int bm0 = blockIdx.y * 128;
  const int bn0 = blockIdx.x * 128;
  const int sec = bn0 >> 8;              // 0=Q, 1=K, 2=V
  const int n_off = bn0 & 255;
  const float* W    = (sec==0) ? Wq : (sec==1) ? Wk : Wv;
  const float* bias = (sec==0) ? bq : (sec==1) ? bk : bv;

  const int tid = threadIdx.x;
  const int warp = tid >> 5, lane = tid & 31;
  const int g = lane >> 2, t = lane & 3;
  const int wm0 = (warp >> 1) * 64;
  const int wn0 = (warp & 1) * 64;
  const uint32_t sb = (uint32_t)__cvta_generic_to_shared(sm);
  const int lr = tid >> 3, lc = (tid & 7) * 4;   // lr 0..15

  float acc[4][8][4];
  #pragma unroll
  for (int i=0;i<4;i++)
    #pragma unroll
    for (int j=0;j<8;j++)
      #pragma unroll
      for (int f=0;f<4;f++) acc[i][j][f]=0.f;

  #define QKV_LOAD(kt, stg) { \
    _Pragma("unroll") \
    for (int i=0;i<8;i++){ \
      int r = lr + i*16; \
      cp16(sb + (((stg)*4608 + r*36 + lc)<<2), x + (size_t)(bm0+r)*DD + (kt)*32 + lc); \
    } \
    _Pragma("unroll") \
    for (int i=0;i<8;i++){ \
      int r = lr + i*16; \
      cp16(sb + ((9216 + (stg)*4608 + r*36 + lc)<<2), W + (size_t)(n_off+r)*DD + (kt)*32 + lc); \
    } \
  }

  QKV_LOAD(0,0); cpcommit();
  for (int kt = 0; kt < 8; kt++){
    const int stg = kt & 1;
    if (kt+1 < 8){ QKV_LOAD(kt+1, stg^1); cpcommit(); cpwait<1>(); }
    else cpwait<0>();
    __syncthreads();

    const uint32_t* As_ = sm + stg*4608;
    const uint32_t* Bs_ = sm + 9216 + stg*4608;
    #pragma unroll
    for (int ks=0; ks<4; ks++){
      const int k0 = ks*8;
      uint32_t af[4][4], bf[8][2];
      #pragma unroll
      for (int mi=0;mi<4;mi++){
        int r = wm0 + mi*16;
        af[mi][0]=f2tf32(__uint_as_float(As_[(r+g  )*36+k0+t]));
        af[mi][1]=f2tf32(__uint_as_float(As_[(r+g+8)*36+k0+t]));
        af[mi][2]=f2tf32(__uint_as_float(As_[(r+g  )*36+k0+t+4]));
        af[mi][3]=f2tf32(__uint_as_float(As_[(r+g+8)*36+k0+t+4]));
      }
      #pragma unroll
      for (int ni=0;ni<8;ni++){
        int c = wn0 + ni*8;
        bf[ni][0]=f2tf32(__uint_as_float(Bs_[(c+g)*36+k0+t]));
        bf[ni][1]=f2tf32(__uint_as_float(Bs_[(c+g)*36+k0+t+4]));
      }
      #pragma unroll
      for (int mi=0;mi<4;mi++)
        #pragma unroll
        for (int ni=0;ni<8;ni++)
          MMA(af[mi][0],af[mi][1],af[mi][2],af[mi][3],bf[ni][0],bf[ni][1],acc[mi][ni]);
    }
    __syncthreads();
  }
  #undef QKV_LOAD

  #pragma unroll
  for (int mi=0;mi<4;mi++){
    #pragma unroll
    for (int ni=0;ni<8;ni++){
      int r0 = bm0 + wm0 + mi*16 + g;
      int c  = n_off + wn0 + ni*8 + 2*t;
      float2 b2 = *(const float2*)(bias + c);
      float v0=acc[mi][ni][0]+b2.x, v1=acc[mi][ni][1]+b2.y;
      float v2=acc[mi][ni][2]+b2.x, v3=acc[mi][ni][3]+b2.y;
      int r1 = r0 + 8;
      if (sec == 0){
        int b0=r0>>11, m0=r0&2047, b1=r1>>11, m1=r1&2047;
        *(float2*)(sp + (size_t)b0*(2LL*LL*DD) + (size_t)m0*DD + c) = make_float2(v0,v1);
        *(float2*)(sp + (size_t)b1*(2LL*LL*DD) + (size_t)m1*DD + c) = make_float2(v2,v3);
        *(float2*)(g_Q + (size_t)r0*DD + c) = make_float2(rndf(v0),rndf(v1));
        *(float2*)(g_Q + (size_t)r1*DD + c) = make_float2(rndf(v2),rndf(v3));
      } else if (sec == 1){
        *(float2*)(g_K + (size_t)r0*DD + c) = make_float2(rndf(v0),rndf(v1));
        *(float2*)(g_K + (size_t)r1*DD + c) = make_float2(rndf(v2),rndf(v3));
      } else {
        *(float2*)(g_V + (size_t)r0*DD + c) = make_float2(rndf(v0),rndf(v1));
        *(float2*)(g_V + (size_t)r1*DD + c) = make_float2(rndf(v2),rndf(v3));
      }
    }
  }
}

// ============================================================
// P-GEMM: P = exp(Q K^T / 16) + fused colsum.
// CTA 128x128, 128 threads, 4 warps of 64x64. Raw tf32 loads (pre-rounded).
// dyn smem: 73728 B
// ============================================================
__global__ __launch_bounds__(128,2) void pexp_gemm(float* __restrict__ Pout)
{
  extern __shared__ uint32_t sm[];
  const int z = blockIdx.z;
  const float* A = g_Q + (size_t)z*LL*DD;
  const float* B = g_K + (size_t)z*LL*DD;
  float* C = Pout + (size_t)z*LL*LL;

  const int bm0 = blockIdx.y * 128;
  const int bn0 = blockIdx.x * 128;
  const int tid = threadIdx.x;
  const int warp = tid >> 5, lane = tid & 31;
  const int g = lane >> 2, t = lane & 3;
  const int wm0 = (warp >> 1) * 64;
  const int wn0 = (warp & 1) * 64;
  const uint32_t sb = (uint32_t)__cvta_generic_to_shared(sm);
  const int lr = tid >> 3, lc = (tid & 7) * 4;

  float acc[4][8][4];
  #pragma unroll
  for (int i=0;i<4;i++)
    #pragma unroll
    for (int j=0;j<8;j++)
      #pragma unroll
      for (int f=0;f<4;f++) acc[i][j][f]=0.f;

  #define P_LOAD(kt, stg) { \
    _Pragma("unroll") \
    for (int i=0;i<8;i++){ \
      int r = lr + i*16; \
      cp16(sb + (((stg)*4608 + r*36 + lc)<<2), A + (size_t)(bm0+r)*DD + (kt)*32 + lc); \
    } \
    _Pragma("unroll") \
    for (int i=0;i<8;i++){ \
      int r = lr + i*16; \
      cp16(sb + ((9216 + (stg)*4608 + r*36 + lc)<<2), B + (size_t)(bn0+r)*DD + (kt)*32 + lc); \
    } \
  }

  P_LOAD(0,0); cpcommit();
  for (int kt = 0; kt < 8; kt++){
    const int stg = kt & 1;
    if (kt+1 < 8){ P_LOAD(kt+1, stg^1); cpcommit(); cpwait<1>(); }
    else cpwait<0>();
    __syncthreads();

    const uint32_t* As_ = sm + stg*4608;
    const uint32_t* Bs_ = sm + 9216 + stg*4608;
    #pragma unroll
    for (int ks=0; ks<4; ks++){
      const int k0 = ks*8;
      uint32_t af[4][4], bf[8][2];
      #pragma unroll
      for (int mi=0;mi<4;mi++){
        int r = wm0 + mi*16;
        af[mi][0]=As_[(r+g  )*36+k0+t];   af[mi][1]=As_[(r+g+8)*36+k0+t];
        af[mi][2]=As_[(r+g  )*36+k0+t+4]; af[mi][3]=As_[(r+g+8)*36+k0+t+4];
      }
      #pragma unroll
      for (int ni=0;ni<8;ni++){
        int c = wn0 + ni*8;
        bf[ni][0]=Bs_[(c+g)*36+k0+t]; bf[ni][1]=Bs_[(c+g)*36+k0+t+4];
      }
      #pragma unroll
      for (int mi=0;mi<4;mi++)
        #pragma unroll
        for (int ni=0;ni<8;ni++)
          MMA(af[mi][0],af[mi][1],af[mi][2],af[mi][3],bf[ni][0],bf[ni][1],acc[mi][ni]);
    }
    __syncthreads();
  }
  #undef P_LOAD

  float csum[8][2];
  #pragma unroll
  for (int ni=0;ni<8;ni++){ csum[ni][0]=0.f; csum[ni][1]=0.f; }

  #pragma unroll
  for (int mi=0;mi<4;mi++){
    #pragma unroll
    for (int ni=0;ni<8;ni++){
      int r0 = bm0 + wm0 + mi*16 + g;
      int c  = bn0 + wn0 + ni*8 + 2*t;
      float e0=__expf(acc[mi][ni][0]*0.0625f), e1=__expf(acc[mi][ni][1]*0.0625f);
      float e2=__expf(acc[mi][ni][2]*0.0625f), e3=__expf(acc[mi][ni][3]*0.0625f);
      *(float2*)(C + (size_t)r0*LL + c)     = make_float2(e0,e1);
      *(float2*)(C + (size_t)(r0+8)*LL + c) = make_float2(e2,e3);
      csum[ni][0] += e0+e2; csum[ni][1] += e1+e3;
    }
  }
  float* sCol = (float*)sm;
  __syncthreads();
  sCol[tid] = 0.f;
  __syncthreads();
  #pragma unroll
  for (int ni=0;ni<8;ni++){
    atomicAdd(&sCol[wn0 + ni*8 + 2*t    ], csum[ni][0]);
    atomicAdd(&sCol[wn0 + ni*8 + 2*t + 1], csum[ni][1]);
  }
  __syncthreads();
  atomicAdd(&g_colsum[z*LL + bn0 + tid], sCol[tid]);
}

// ============================================================
// AV GEMM: C = (P/colsum) @ V, normalized A written back in place.
// BM=64, BN=256, BK=32, 128 threads, 4 warps of 64x64.
// A: LDG+scale+STG+raw tf32. B: cp.async of g_V [k][d], stride 260.
// dyn smem: (2*64*36 + 2*32*260)*4 = 84992 B
// ============================================================
__global__ __launch_bounds__(128,2) void gemm_av(
    float* __restrict__ P, float* __restrict__ Cg)
{
  extern __shared__ uint32_t sm[];
  const int z = blockIdx.z;
  float* A = P + (size_t)z*LL*LL;
  const float* B = g_V + (size_t)z*LL*DD;
  float* C = Cg + (size_t)z*(2LL*LL*DD);
  const float* inv = g_colsum + z*LL;

  const int bm0 = blockIdx.y * 64;
  const int tid = threadIdx.x;
  const int warp = tid >> 5, lane = tid & 31;
  const int g = lane >> 2, t = lane & 3;
  const int wn0 = warp * 64;
  const uint32_t sb = (uint32_t)__cvta_generic_to_shared(sm);
  const int lr = tid >> 3, lc = (tid & 7) * 4;   // lr 0..15

  float acc[4][8][4];
  #pragma unroll
  for (int i=0;i<4;i++)
    #pragma unroll
    for (int j=0;j<8;j++)
      #pragma unroll
      for (int f=0;f<4;f++) acc[i][j][f]=0.f;

  uint32_t areg[16];

  #define PROC_A(kt) { \
    float4 iv = *(const float4*)(inv + (kt)*32 + lc); \
    _Pragma("unroll") \
    for (int i=0;i<4;i++){ \
      float* ap = A + (size_t)(bm0 + lr + i*16)*LL + (kt)*32 + lc; \
      float4 p = *(const float4*)ap; \
      p.x*=iv.x; p.y*=iv.y; p.z*=iv.z; p.w*=iv.w; \
      *(float4*)ap = p; \
      areg[i*4+0]=__float_as_uint(p.x); areg[i*4+1]=__float_as_uint(p.y); \
      areg[i*4+2]=__float_as_uint(p.z); areg[i*4+3]=__float_as_uint(p.w); \
    } \
  }
  #define LOAD_B(kt, stg) { \
    _Pragma("unroll") \
    for (int i=0;i<16;i++){ \
      int s = tid + i*128; int kk = s>>6; int ch=(s&63)*4; \
      cp16(sb + ((4608 + (stg)*8320 + kk*260 + ch)<<2), B + (size_t)((kt)*32+kk)*DD + ch); \
    } \
  }

  PROC_A(0);
  LOAD_B(0,0); cpcommit();

  const int nk = LL/32;   // 64
  for (int kt = 0; kt < nk; kt++){
    const int stg = kt & 1;
    #pragma unroll
    for (int i=0;i<4;i++){
      uint32_t* d = sm + stg*2304 + (lr + i*16)*36 + lc;
      *(uint4*)d = make_uint4(areg[i*4],areg[i*4+1],areg[i*4+2],areg[i*4+3]);
    }
    const bool more = (kt + 1 < nk);
    float4 rawp[4]; float4 iv;
    if (more){
      LOAD_B(kt+1, stg^1); cpcommit();
      iv = *(const float4*)(inv + (kt+1)*32 + lc);
      #pragma unroll
      for (int i=0;i<4;i++)
        rawp[i] = *(const float4*)(A + (size_t)(bm0 + lr + i*16)*LL + (kt+1)*32 + lc);
      cpwait<1>();
    } else {
      cpwait<0>();
    }
    __syncthreads();

    const uint32_t* As_ = sm + stg*2304;
    const uint32_t* Bs_ = sm + 4608 + stg*8320;
    #pragma unroll
    for (int ks=0; ks<4; ks++){
      const int k0 = ks*8;
      uint32_t af[4][4], bf[8][2];
      #pragma unroll
      for (int mi=0;mi<4;mi++){
        int r = mi*16;
        af[mi][0]=As_[(r+g  )*36+k0+t];   af[mi][1]=As_[(r+g+8)*36+k0+t];
        af[mi][2]=As_[(r+g  )*36+k0+t+4]; af[mi][3]=As_[(r+g+8)*36+k0+t+4];
      }
      #pragma unroll
      for (int ni=0;ni<8;ni++){
        int c = wn0 + ni*8;
        bf[ni][0]=Bs_[(k0+t  )*260 + c+g];
        bf[ni][1]=Bs_[(k0+t+4)*260 + c+g];
      }
      #pragma unroll
      for (int mi=0;mi<4;mi++)
        #pragma unroll
        for (int ni=0;ni<8;ni++)
          MMA(af[mi][0],af[mi][1],af[mi][2],af[mi][3],bf[ni][0],bf[ni][1],acc[mi][ni]);
    }

    if (more){
      #pragma unroll
      for (int i=0;i<4;i++){
        float4 p = rawp[i];
        p.x*=iv.x; p.y*=iv.y; p.z*=iv.z; p.w*=iv.w;
        *(float4*)(A + (size_t)(bm0 + lr + i*16)*LL + (kt+1)*32 + lc) = p;
        areg[i*4+0]=__float_as_uint(p.x); areg[i*4+1]=__float_as_uint(p.y);
        areg[i*4+2]=__float_as_uint(p.z); areg[i*4+3]=__float_as_uint(p.w);
      }
    }
    __syncthreads();
  }
  #undef PROC_A
  #undef LOAD_B

  #pragma unroll
  for (int mi=0;mi<4;mi++){
    #pragma unroll
    for (int ni=0;ni<8;ni++){
      int r = bm0 + mi*16 + g;
      int c = wn0 + ni*8 + 2*t;
      *(float2*)(C + (size_t)r*DD + c)     = make_float2(acc[mi][ni][0],acc[mi][ni][1]);
      *(float2*)(C + (size_t)(r+8)*DD + c) = make_float2(acc[mi][ni][2],acc[mi][ni][3]);
    }
  }
}

// ============================================================
extern "C" void kernel_launch(void* const* d_in, const int* in_sizes, int n_in,
                              void* d_out, int out_size)
{
  const float* x  = (const float*)d_in[0];
  const float* Wq = (const float*)d_in[1];
  const float* bq = (const float*)d_in[2];
  const float* Wk = (const float*)d_in[3];
  const float* bk = (const float*)d_in[4];
  const float* Wv = (const float*)d_in[5];
  const float* bv = (const float*)d_in[6];

  float* sp   = (float*)d_out;                  // S_p [B, 2L, D]
  float* Aout = sp + (size_t)BB*2*LL*DD;        // A   [B, L, L]

  const int SM128 = 73728, SMAV = 84992;
  cudaFuncSetAttribute(qkv_gemm,  cudaFuncAttributeMaxDynamicSharedMemorySize, SM128);
  cudaFuncSetAttribute(pexp_gemm, cudaFuncAttributeMaxDynamicSharedMemorySize, SM128);
  cudaFuncSetAttribute(gemm_av,   cudaFuncAttributeMaxDynamicSharedMemorySize, SMAV);

  zerocs_kernel<<<BB*LL/256, 256>>>();

  // Fused QKV projection
  qkv_gemm<<<dim3(6,128,1), 128, SM128>>>(x, Wq, bq, Wk, bk, Wv, bv, sp);

  // P = exp(Q K^T / 16) + fused column sums
  pexp_gemm<<<dim3(16,16,BB), 128, SM128>>>(Aout);

  invcs_kernel<<<BB*LL/256, 256>>>();

  // C = (P/colsum) @ V with fused in-place normalization of A
  gemm_av<<<dim3(1,32,BB), 128, SMAV>>>(Aout, sp + (size_t)LL*DD);
}

// round 10
// speedup vs baseline: 1.3351x; 1.2295x over previous
#include <cuda_runtime.h>
#include <cuda_fp16.h>
#include <cstdint>
#include <math.h>

#define BB 8
#define LL 2048
#define DD 256

// Scratch (__device__ globals)
__device__ __align__(16) __half g_Qh[BB*LL*DD];    // fp16 Q+bias  [b][l][d]
__device__ __align__(16) __half g_Kh[BB*LL*DD];    // fp16 K+bias  [b][l][d]
__device__ __align__(16) __half g_VTh[BB*DD*LL];   // fp16 V+bias transposed [b][d][l]
__device__ __align__(16) float  g_colsum[BB*LL];   // colsum -> inverted in place

__device__ __forceinline__ uint32_t f2tf32(float x){
  uint32_t u; asm("cvt.rna.tf32.f32 %0, %1;" : "=r"(u) : "f"(x)); return u;
}
__device__ __forceinline__ uint32_t h2u(__half2 h){
  union { __half2 h; uint32_t u; } cvt; cvt.h = h; return cvt.u;
}

__device__ __forceinline__ void cp16(uint32_t dst, const void* src){
  asm volatile("cp.async.cg.shared.global [%0], [%1], 16;\n" :: "r"(dst), "l"(src));
}
__device__ __forceinline__ void cpcommit(){ asm volatile("cp.async.commit_group;\n"); }
template<int N> __device__ __forceinline__ void cpwait(){
  asm volatile("cp.async.wait_group %0;\n" :: "n"(N));
}

// tf32 m16n8k8 (QKV only)
#define MMAT(a0,a1,a2,a3,b0,b1,c) \
  asm volatile("mma.sync.aligned.m16n8k8.row.col.f32.tf32.tf32.f32 " \
    "{%0,%1,%2,%3}, {%4,%5,%6,%7}, {%8,%9}, {%0,%1,%2,%3};" \
    : "+f"(c[0]),"+f"(c[1]),"+f"(c[2]),"+f"(c[3]) \
    : "r"(a0),"r"(a1),"r"(a2),"r"(a3),"r"(b0),"r"(b1))

// fp16 m16n8k16, fp32 accum
#define MMAH(a0,a1,a2,a3,b0,b1,c) \
  asm volatile("mma.sync.aligned.m16n8k16.row.col.f32.f16.f16.f32 " \
    "{%0,%1,%2,%3}, {%4,%5,%6,%7}, {%8,%9}, {%0,%1,%2,%3};" \
    : "+f"(c[0]),"+f"(c[1]),"+f"(c[2]),"+f"(c[3]) \
    : "r"(a0),"r"(a1),"r"(a2),"r"(a3),"r"(b0),"r"(b1))

__global__ void invcs_kernel(){
  int i = blockIdx.x*256 + threadIdx.x;
  g_colsum[i] = 1.0f / g_colsum[i];
}
__global__ void zerocs_kernel(){
  int i = blockIdx.x*256 + threadIdx.x;
  g_colsum[i] = 0.f;
}

// ============================================================
// Fused QKV GEMM (tf32). M=16384, N=768 (Q|K|V), K=256.
// CTA 128x128, 128 threads, 4 warps of 64x64.
// Epilogue: Q -> sp (fp32) + g_Qh; K -> g_Kh; V -> g_VTh (transposed).
// dyn smem: 73728 B
// ============================================================
__global__ __launch_bounds__(128,2) void qkv_gemm(
    const float* __restrict__ x,
    const float* __restrict__ Wq, const float* __restrict__ bq,
    const float* __restrict__ Wk, const float* __restrict__ bk,
    const float* __restrict__ Wv, const float* __restrict__ bv,
    float* __restrict__ sp)
{
  extern __shared__ uint32_t sm[];
  const int bm0 = blockIdx.y * 128;
  const int bn0 = blockIdx.x * 128;
  const int sec = bn0 >> 8;              // 0=Q, 1=K, 2=V
  const int n_off = bn0 & 255;
  const float* W    = (sec==0) ? Wq : (sec==1) ? Wk : Wv;
  const float* bias = (sec==0) ? bq : (sec==1) ? bk : bv;

  const int tid = threadIdx.x;
  const int warp = tid >> 5, lane = tid & 31;
  const int g = lane >> 2, t = lane & 3;
  const int wm0 = (warp >> 1) * 64;
  const int wn0 = (warp & 1) * 64;
  const uint32_t sb = (uint32_t)__cvta_generic_to_shared(sm);
  const int lr = tid >> 3, lc = (tid & 7) * 4;

  float acc[4][8][4];
  #pragma unroll
  for (int i=0;i<4;i++)
    #pragma unroll
    for (int j=0;j<8;j++)
      #pragma unroll
      for (int f=0;f<4;f++) acc[i][j][f]=0.f;

  #define QKV_LOAD(kt, stg) { \
    _Pragma("unroll") \
    for (int i=0;i<8;i++){ \
      int r = lr + i*16; \
      cp16(sb + (((stg)*4608 + r*36 + lc)<<2), x + (size_t)(bm0+r)*DD + (kt)*32 + lc); \
    } \
    _Pragma("unroll") \
    for (int i=0;i<8;i++){ \
      int r = lr + i*16; \
      cp16(sb + ((9216 + (stg)*4608 + r*36 + lc)<<2), W + (size_t)(n_off+r)*DD + (kt)*32 + lc); \
    } \
  }

  QKV_LOAD(0,0); cpcommit();
  for (int kt = 0; kt < 8; kt++){
    const int stg = kt & 1;
    if (kt+1 < 8){ QKV_LOAD(kt+1, stg^1); cpcommit(); cpwait<1>(); }
    else cpwait<0>();
    __syncthreads();

    const uint32_t* As_ = sm + stg*4608;
    const uint32_t* Bs_ = sm + 9216 + stg*4608;
    #pragma unroll
    for (int ks=0; ks<4; ks++){
      const int k0 = ks*8;
      uint32_t af[4][4], bf[8][2];
      #pragma unroll
      for (int mi=0;mi<4;mi++){
        int r = wm0 + mi*16;
        af[mi][0]=f2tf32(__uint_as_float(As_[(r+g  )*36+k0+t]));
        af[mi][1]=f2tf32(__uint_as_float(As_[(r+g+8)*36+k0+t]));
        af[mi][2]=f2tf32(__uint_as_float(As_[(r+g  )*36+k0+t+4]));
        af[mi][3]=f2tf32(__uint_as_float(As_[(r+g+8)*36+k0+t+4]));
      }
      #pragma unroll
      for (int ni=0;ni<8;ni++){
        int c = wn0 + ni*8;
        bf[ni][0]=f2tf32(__uint_as_float(Bs_[(c+g)*36+k0+t]));
        bf[ni][1]=f2tf32(__uint_as_float(Bs_[(c+g)*36+k0+t+4]));
      }
      #pragma unroll
      for (int mi=0;mi<4;mi++)
        #pragma unroll
        for (int ni=0;ni<8;ni++)
          MMAT(af[mi][0],af[mi][1],af[mi][2],af[mi][3],bf[ni][0],bf[ni][1],acc[mi][ni]);
    }
    __syncthreads();
  }
  #undef QKV_LOAD

  #pragma unroll
  for (int mi=0;mi<4;mi++){
    #pragma unroll
    for (int ni=0;ni<8;ni++){
      int r0 = bm0 + wm0 + mi*16 + g;
      int c  = n_off + wn0 + ni*8 + 2*t;
      float2 b2 = *(const float2*)(bias + c);
      float v0=acc[mi][ni][0]+b2.x, v1=acc[mi][ni][1]+b2.y;
      float v2=acc[mi][ni][2]+b2.x, v3=acc[mi][ni][3]+b2.y;
      int r1 = r0 + 8;
      if (sec == 0){
        int b0=r0>>11, m0=r0&2047, b1=r1>>11, m1=r1&2047;
        *(float2*)(sp + (size_t)b0*(2LL*LL*DD) + (size_t)m0*DD + c) = make_float2(v0,v1);
        *(float2*)(sp + (size_t)b1*(2LL*LL*DD) + (size_t)m1*DD + c) = make_float2(v2,v3);
        *(__half2*)(g_Qh + (size_t)r0*DD + c) = __floats2half2_rn(v0,v1);
        *(__half2*)(g_Qh + (size_t)r1*DD + c) = __floats2half2_rn(v2,v3);
      } else if (sec == 1){
        *(__half2*)(g_Kh + (size_t)r0*DD + c) = __floats2half2_rn(v0,v1);
        *(__half2*)(g_Kh + (size_t)r1*DD + c) = __floats2half2_rn(v2,v3);
      } else {
        // V transposed: VT[b][d][l]; r is global row b*L+l, d = c
        int b0=r0>>11, m0=r0&2047, b1=r1>>11, m1=r1&2047;
        __half* VT0 = g_VTh + (size_t)b0*DD*LL;
        __half* VT1 = g_VTh + (size_t)b1*DD*LL;
        VT0[(size_t)(c  )*LL + m0] = __float2half_rn(v0);
        VT0[(size_t)(c+1)*LL + m0] = __float2half_rn(v1);
        VT1[(size_t)(c  )*LL + m1] = __float2half_rn(v2);
        VT1[(size_t)(c+1)*LL + m1] = __float2half_rn(v3);
      }
    }
  }
}

// ============================================================
// P-GEMM fp16: P = exp(Q K^T / 16) + fused colsum.
// CTA 128x128, 128 threads, 4 warps of 64x64, m16n8k16.
// smem (half2 units, stride 20): A 2x2560, B 2x2560 -> 40960 B
// ============================================================
__global__ __launch_bounds__(128,2) void pexp_gemm(float* __restrict__ Pout)
{
  extern __shared__ uint32_t sm[];
  const int z = blockIdx.z;
  const __half* A = g_Qh + (size_t)z*LL*DD;
  const __half* B = g_Kh + (size_t)z*LL*DD;
  float* C = Pout + (size_t)z*LL*LL;

  const int bm0 = blockIdx.y * 128;
  const int bn0 = blockIdx.x * 128;
  const int tid = threadIdx.x;
  const int warp = tid >> 5, lane = tid & 31;
  const int g = lane >> 2, t = lane & 3;
  const int wm0 = (warp >> 1) * 64;
  const int wn0 = (warp & 1) * 64;
  const uint32_t sb = (uint32_t)__cvta_generic_to_shared(sm);
  const int lr4 = tid >> 2;             // 0..31
  const int lc4 = (tid & 3) * 4;        // half2 units: 0,4,8,12

  float acc[4][8][4];
  #pragma unroll
  for (int i=0;i<4;i++)
    #pragma unroll
    for (int j=0;j<8;j++)
      #pragma unroll
      for (int f=0;f<4;f++) acc[i][j][f]=0.f;

  #define P_LOAD(kt, stg) { \
    _Pragma("unroll") \
    for (int i=0;i<4;i++){ \
      int r = lr4 + i*32; \
      cp16(sb + (((stg)*2560 + r*20 + lc4)<<2), A + (size_t)(bm0+r)*DD + (kt)*32 + lc4*2); \
    } \
    _Pragma("unroll") \
    for (int i=0;i<4;i++){ \
      int r = lr4 + i*32; \
      cp16(sb + ((5120 + (stg)*2560 + r*20 + lc4)<<2), B + (size_t)(bn0+r)*DD + (kt)*32 + lc4*2); \
    } \
  }

  P_LOAD(0,0); cpcommit();
  for (int kt = 0; kt < 8; kt++){
    const int stg = kt & 1;
    if (kt+1 < 8){ P_LOAD(kt+1, stg^1); cpcommit(); cpwait<1>(); }
    else cpwait<0>();
    __syncthreads();

    const uint32_t* As_ = sm + stg*2560;
    const uint32_t* Bs_ = sm + 5120 + stg*2560;
    #pragma unroll
    for (int ks=0; ks<2; ks++){
      const int k0 = ks*8;               // half2 units (16 halves per step)
      uint32_t af[4][4], bf[8][2];
      #pragma unroll
      for (int mi=0;mi<4;mi++){
        int r = wm0 + mi*16;
        af[mi][0]=As_[(r+g  )*20 + k0 + t];
        af[mi][1]=As_[(r+g+8)*20 + k0 + t];
        af[mi][2]=As_[(r+g  )*20 + k0 + t+4];
        af[mi][3]=As_[(r+g+8)*20 + k0 + t+4];
      }
      #pragma unroll
      for (int ni=0;ni<8;ni++){
        int c = wn0 + ni*8;
        bf[ni][0]=Bs_[(c+g)*20 + k0 + t];
        bf[ni][1]=Bs_[(c+g)*20 + k0 + t+4];
      }
      #pragma unroll
      for (int mi=0;mi<4;mi++)
        #pragma unroll
        for (int ni=0;ni<8;ni++)
          MMAH(af[mi][0],af[mi][1],af[mi][2],af[mi][3],bf[ni][0],bf[ni][1],acc[mi][ni]);
    }
    __syncthreads();
  }
  #undef P_LOAD

  float csum[8][2];
  #pragma unroll
  for (int ni=0;ni<8;ni++){ csum[ni][0]=0.f; csum[ni][1]=0.f; }

  #pragma unroll
  for (int mi=0;mi<4;mi++){
    #pragma unroll
    for (int ni=0;ni<8;ni++){
      int r0 = bm0 + wm0 + mi*16 + g;
      int c  = bn0 + wn0 + ni*8 + 2*t;
      float e0=__expf(acc[mi][ni][0]*0.0625f), e1=__expf(acc[mi][ni][1]*0.0625f);
      float e2=__expf(acc[mi][ni][2]*0.0625f), e3=__expf(acc[mi][ni][3]*0.0625f);
      *(float2*)(C + (size_t)r0*LL + c)     = make_float2(e0,e1);
      *(float2*)(C + (size_t)(r0+8)*LL + c) = make_float2(e2,e3);
      csum[ni][0] += e0+e2; csum[ni][1] += e1+e3;
    }
  }
  float* sCol = (float*)sm;
  __syncthreads();
  sCol[tid] = 0.f;
  __syncthreads();
  #pragma unroll
  for (int ni=0;ni<8;ni++){
    atomicAdd(&sCol[wn0 + ni*8 + 2*t    ], csum[ni][0]);
    atomicAdd(&sCol[wn0 + ni*8 + 2*t + 1], csum[ni][1]);
  }
  __syncthreads();
  atomicAdd(&g_colsum[z*LL + bn0 + tid], sCol[tid]);
}

// ============================================================
// AV GEMM fp16: C = (P/colsum) @ V. BM=64, BN=256, 128 threads,
// 4 warps 64x64, m16n8k16. A: LDG fp32 + normalize + STG + half2(x64).
// B: cp.async of g_VTh [d][k].
// smem half2: As 2x1280, Bs 2x5120 -> 51200 B
// ============================================================
__global__ __launch_bounds__(128,2) void gemm_av(
    float* __restrict__ P, float* __restrict__ Cg)
{
  extern __shared__ uint32_t sm[];
  const int z = blockIdx.z;
  float* A = P + (size_t)z*LL*LL;
  const __half* B = g_VTh + (size_t)z*DD*LL;
  float* C = Cg + (size_t)z*(2LL*LL*DD);
  const float* inv = g_colsum + z*LL;

  const int bm0 = blockIdx.y * 64;
  const int tid = threadIdx.x;
  const int warp = tid >> 5, lane = tid & 31;
  const int g = lane >> 2, t = lane & 3;
  const int wn0 = warp * 64;
  const uint32_t sb = (uint32_t)__cvta_generic_to_shared(sm);
  const int ar = tid >> 3, af4 = (tid & 7) * 4;   // A loader: row 0..15, float col
  const int br = tid >> 2, bc4 = (tid & 3) * 4;   // B loader: row 0..31, half2 col

  float acc[4][8][4];
  #pragma unroll
  for (int i=0;i<4;i++)
    #pragma unroll
    for (int j=0;j<8;j++)
      #pragma unroll
      for (int f=0;f<4;f++) acc[i][j][f]=0.f;

  uint32_t areg[8];   // 4 rows x 2 half2

  #define PROC_A(kt) { \
    float4 iv = *(const float4*)(inv + (kt)*32 + af4); \
    _Pragma("unroll") \
    for (int i=0;i<4;i++){ \
      float* ap = A + (size_t)(bm0 + ar + i*16)*LL + (kt)*32 + af4; \
      float4 p = *(const float4*)ap; \
      p.x*=iv.x; p.y*=iv.y; p.z*=iv.z; p.w*=iv.w; \
      *(float4*)ap = p; \
      areg[i*2+0]=h2u(__floats2half2_rn(p.x*64.f, p.y*64.f)); \
      areg[i*2+1]=h2u(__floats2half2_rn(p.z*64.f, p.w*64.f)); \
    } \
  }
  #define LOAD_B(kt, stg) { \
    _Pragma("unroll") \
    for (int i=0;i<8;i++){ \
      int d = br + i*32; \
      cp16(sb + ((2560 + (stg)*5120 + d*20 + bc4)<<2), B + (size_t)d*LL + (kt)*32 + bc4*2); \
    } \
  }

  PROC_A(0);
  LOAD_B(0,0); cpcommit();

  const int nk = LL/32;   // 64
  for (int kt = 0; kt < nk; kt++){
    const int stg = kt & 1;
    #pragma unroll
    for (int i=0;i<4;i++){
      uint32_t* d = sm + stg*1280 + (ar + i*16)*20 + (tid&7)*2;
      *(uint2*)d = make_uint2(areg[i*2], areg[i*2+1]);
    }
    const bool more = (kt + 1 < nk);
    float4 rawp[4]; float4 iv;
    if (more){
      LOAD_B(kt+1, stg^1); cpcommit();
      iv = *(const float4*)(inv + (kt+1)*32 + af4);
      #pragma unroll
      for (int i=0;i<4;i++)
        rawp[i] = *(const float4*)(A + (size_t)(bm0 + ar + i*16)*LL + (kt+1)*32 + af4);
      cpwait<1>();
    } else {
      cpwait<0>();
    }
    __syncthreads();

    const uint32_t* As_ = sm + stg*1280;
    const uint32_t* Bs_ = sm + 2560 + stg*5120;
    #pragma unroll
    for (int ks=0; ks<2; ks++){
      const int k0 = ks*8;
      uint32_t af[4][4], bf[8][2];
      #pragma unroll
      for (int mi=0;mi<4;mi++){
        int r = mi*16;
        af[mi][0]=As_[(r+g  )*20 + k0 + t];
        af[mi][1]=As_[(r+g+8)*20 + k0 + t];
        af[mi][2]=As_[(r+g  )*20 + k0 + t+4];
        af[mi][3]=As_[(r+g+8)*20 + k0 + t+4];
      }
      #pragma unroll
      for (int ni=0;ni<8;ni++){
        int c = wn0 + ni*8;
        bf[ni][0]=Bs_[(c+g)*20 + k0 + t];
        bf[ni][1]=Bs_[(c+g)*20 + k0 + t+4];
      }
      #pragma unroll
      for (int mi=0;mi<4;mi++)
        #pragma unroll
        for (int ni=0;ni<8;ni++)
          MMAH(af[mi][0],af[mi][1],af[mi][2],af[mi][3],bf[ni][0],bf[ni][1],acc[mi][ni]);
    }

    if (more){
      #pragma unroll
      for (int i=0;i<4;i++){
        float4 p = rawp[i];
        p.x*=iv.x; p.y*=iv.y; p.z*=iv.z; p.w*=iv.w;
        *(float4*)(A + (size_t)(bm0 + ar + i*16)*LL + (kt+1)*32 + af4) = p;
        areg[i*2+0]=h2u(__floats2half2_rn(p.x*64.f, p.y*64.f));
        areg[i*2+1]=h2u(__floats2half2_rn(p.z*64.f, p.w*64.f));
      }
    }
    __syncthreads();
  }
  #undef PROC_A
  #undef LOAD_B

  const float s = 0.015625f;  // 1/64
  #pragma unroll
  for (int mi=0;mi<4;mi++){
    #pragma unroll
    for (int ni=0;ni<8;ni++){
      int r = bm0 + mi*16 + g;
      int c = wn0 + ni*8 + 2*t;
      *(float2*)(C + (size_t)r*DD + c)     = make_float2(acc[mi][ni][0]*s,acc[mi][ni][1]*s);
      *(float2*)(C + (size_t)(r+8)*DD + c) = make_float2(acc[mi][ni][2]*s,acc[mi][ni][3]*s);
    }
  }
}

// ============================================================
extern "C" void kernel_launch(void* const* d_in, const int* in_sizes, int n_in,
                              void* d_out, int out_size)
{
  const float* x  = (const float*)d_in[0];
  const float* Wq = (const float*)d_in[1];
  const float* bq = (const float*)d_in[2];
  const float* Wk = (const float*)d_in[3];
  const float* bk = (const float*)d_in[4];
  const float* Wv = (const float*)d_in[5];
  const float* bv = (const float*)d_in[6];

  float* sp   = (float*)d_out;                  // S_p [B, 2L, D]
  float* Aout = sp + (size_t)BB*2*LL*DD;        // A   [B, L, L]

  const int SMQKV = 73728, SMP = 40960, SMAV = 51200;
  cudaFuncSetAttribute(qkv_gemm,  cudaFuncAttributeMaxDynamicSharedMemorySize, SMQKV);
  cudaFuncSetAttribute(pexp_gemm, cudaFuncAttributeMaxDynamicSharedMemorySize, SMP);
  cudaFuncSetAttribute(gemm_av,   cudaFuncAttributeMaxDynamicSharedMemorySize, SMAV);

  zerocs_kernel<<<BB*LL/256, 256>>>();

  // Fused QKV projection (tf32), emits fp16 Q/K/V^T
  qkv_gemm<<<dim3(6,128,1), 128, SMQKV>>>(x, Wq, bq, Wk, bk, Wv, bv, sp);

  // P = exp(Q K^T / 16) + fused column sums (fp16 mma)
  pexp_gemm<<<dim3(16,16,BB), 128, SMP>>>(Aout);

  invcs_kernel<<<BB*LL/256, 256>>>();

  // C = (P/colsum) @ V with fused in-place normalization (fp16 mma)
  gemm_av<<<dim3(1,32,BB), 128, SMAV>>>(Aout, sp + (size_t)LL*DD);
}

// round 12
// speedup vs baseline: 1.4959x; 1.1204x over previous
#include <cuda_runtime.h>
#include <cuda_fp16.h>
#include <cstdint>
#include <math.h>

#define BB 8
#define LL 2048
#define DD 256

// Scratch (__device__ globals)
__device__ __align__(16) __half g_Qh[BB*LL*DD];    // fp16 Q+bias  [b][l][d]
__device__ __align__(16) __half g_Kh[BB*LL*DD];    // fp16 K+bias  [b][l][d]
__device__ __align__(16) __half g_VTh[BB*DD*LL];   // fp16 V+bias transposed [b][d][l]
__device__ __align__(16) __half g_Ph[BB*LL*LL];    // fp16 unnormalized P
__device__ __align__(16) float  g_colsum[BB*LL];   // colsum -> inverted in place

__device__ __forceinline__ uint32_t f2tf32(float x){
  uint32_t u; asm("cvt.rna.tf32.f32 %0, %1;" : "=r"(u) : "f"(x)); return u;
}
__device__ __forceinline__ uint32_t h2u(__half2 h){
  union { __half2 h; uint32_t u; } cvt; cvt.h = h; return cvt.u;
}
__device__ __forceinline__ __half2 u2h(uint32_t u){
  union { uint32_t u; __half2 h; } cvt; cvt.u = u; return cvt.h;
}

__device__ __forceinline__ void cp16(uint32_t dst, const void* src){
  asm volatile("cp.async.cg.shared.global [%0], [%1], 16;\n" :: "r"(dst), "l"(src));
}
__device__ __forceinline__ void cpcommit(){ asm volatile("cp.async.commit_group;\n"); }
template<int N> __device__ __forceinline__ void cpwait(){
  asm volatile("cp.async.wait_group %0;\n" :: "n"(N));
}

// tf32 m16n8k8 (QKV only)
#define MMAT(a0,a1,a2,a3,b0,b1,c) \
  asm volatile("mma.sync.aligned.m16n8k8.row.col.f32.tf32.tf32.f32 " \
    "{%0,%1,%2,%3}, {%4,%5,%6,%7}, {%8,%9}, {%0,%1,%2,%3};" \
    : "+f"(c[0]),"+f"(c[1]),"+f"(c[2]),"+f"(c[3]) \
    : "r"(a0),"r"(a1),"r"(a2),"r"(a3),"r"(b0),"r"(b1))

// fp16 m16n8k16, fp32 accum
#define MMAH(a0,a1,a2,a3,b0,b1,c) \
  asm volatile("mma.sync.aligned.m16n8k16.row.col.f32.f16.f16.f32 " \
    "{%0,%1,%2,%3}, {%4,%5,%6,%7}, {%8,%9}, {%0,%1,%2,%3};" \
    : "+f"(c[0]),"+f"(c[1]),"+f"(c[2]),"+f"(c[3]) \
    : "r"(a0),"r"(a1),"r"(a2),"r"(a3),"r"(b0),"r"(b1))

__global__ void invcs_kernel(){
  int i = blockIdx.x*256 + threadIdx.x;
  g_colsum[i] = 1.0f / g_colsum[i];
}
__global__ void zerocs_kernel(){
  int i = blockIdx.x*256 + threadIdx.x;
  g_colsum[i] = 0.f;
}

// ============================================================
// Fused QKV GEMM (tf32). M=16384, N=768 (Q|K|V), K=256.
// CTA 128x128, 128 threads, 4 warps of 64x64.
// Epilogue: Q -> sp (fp32) + g_Qh; K -> g_Kh; V -> g_VTh (transposed).
// dyn smem: 73728 B
// ============================================================
__global__ __launch_bounds__(128,2) void qkv_gemm(
    const float* __restrict__ x,
    const float* __restrict__ Wq, const float* __restrict__ bq,
    const float* __restrict__ Wk, const float* __restrict__ bk,
    const float* __restrict__ Wv, const float* __restrict__ bv,
    float* __restrict__ sp)
{
  extern __shared__ uint32_t sm[];
  const int bm0 = blockIdx.y * 128;
  const int bn0 = blockIdx.x * 128;
  const int sec = bn0 >> 8;              // 0=Q, 1=K, 2=V
  const int n_off = bn0 & 255;
  const float* W    = (sec==0) ? Wq : (sec==1) ? Wk : Wv;
  const float* bias = (sec==0) ? bq : (sec==1) ? bk : bv;

  const int tid = threadIdx.x;
  const int warp = tid >> 5, lane = tid & 31;
  const int g = lane >> 2, t = lane & 3;
  const int wm0 = (warp >> 1) * 64;
  const int wn0 = (warp & 1) * 64;
  const uint32_t sb = (uint32_t)__cvta_generic_to_shared(sm);
  const int lr = tid >> 3, lc = (tid & 7) * 4;

  float acc[4][8][4];
  #pragma unroll
  for (int i=0;i<4;i++)
    #pragma unroll
    for (int j=0;j<8;j++)
      #pragma unroll
      for (int f=0;f<4;f++) acc[i][j][f]=0.f;

  #define QKV_LOAD(kt, stg) { \
    _Pragma("unroll") \
    for (int i=0;i<8;i++){ \
      int r = lr + i*16; \
      cp16(sb + (((stg)*4608 + r*36 + lc)<<2), x + (size_t)(bm0+r)*DD + (kt)*32 + lc); \
    } \
    _Pragma("unroll") \
    for (int i=0;i<8;i++){ \
      int r = lr + i*16; \
      cp16(sb + ((9216 + (stg)*4608 + r*36 + lc)<<2), W + (size_t)(n_off+r)*DD + (kt)*32 + lc); \
    } \
  }

  QKV_LOAD(0,0); cpcommit();
  for (int kt = 0; kt < 8; kt++){
    const int stg = kt & 1;
    if (kt+1 < 8){ QKV_LOAD(kt+1, stg^1); cpcommit(); cpwait<1>(); }
    else cpwait<0>();
    __syncthreads();

    const uint32_t* As_ = sm + stg*4608;
    const uint32_t* Bs_ = sm + 9216 + stg*4608;
    #pragma unroll
    for (int ks=0; ks<4; ks++){
      const int k0 = ks*8;
      uint32_t af[4][4], bf[8][2];
      #pragma unroll
      for (int mi=0;mi<4;mi++){
        int r = wm0 + mi*16;
        af[mi][0]=f2tf32(__uint_as_float(As_[(r+g  )*36+k0+t]));
        af[mi][1]=f2tf32(__uint_as_float(As_[(r+g+8)*36+k0+t]));
        af[mi][2]=f2tf32(__uint_as_float(As_[(r+g  )*36+k0+t+4]));
        af[mi][3]=f2tf32(__uint_as_float(As_[(r+g+8)*36+k0+t+4]));
      }
      #pragma unroll
      for (int ni=0;ni<8;ni++){
        int c = wn0 + ni*8;
        bf[ni][0]=f2tf32(__uint_as_float(Bs_[(c+g)*36+k0+t]));
        bf[ni][1]=f2tf32(__uint_as_float(Bs_[(c+g)*36+k0+t+4]));
      }
      #pragma unroll
      for (int mi=0;mi<4;mi++)
        #pragma unroll
        for (int ni=0;ni<8;ni++)
          MMAT(af[mi][0],af[mi][1],af[mi][2],af[mi][3],bf[ni][0],bf[ni][1],acc[mi][ni]);
    }
    __syncthreads();
  }
  #undef QKV_LOAD

  #pragma unroll
  for (int mi=0;mi<4;mi++){
    #pragma unroll
    for (int ni=0;ni<8;ni++){
      int r0 = bm0 + wm0 + mi*16 + g;
      int c  = n_off + wn0 + ni*8 + 2*t;
      float2 b2 = *(const float2*)(bias + c);
      float v0=acc[mi][ni][0]+b2.x, v1=acc[mi][ni][1]+b2.y;
      float v2=acc[mi][ni][2]+b2.x, v3=acc[mi][ni][3]+b2.y;
      int r1 = r0 + 8;
      if (sec == 0){
        int b0=r0>>11, m0=r0&2047, b1=r1>>11, m1=r1&2047;
        *(float2*)(sp + (size_t)b0*(2LL*LL*DD) + (size_t)m0*DD + c) = make_float2(v0,v1);
        *(float2*)(sp + (size_t)b1*(2LL*LL*DD) + (size_t)m1*DD + c) = make_float2(v2,v3);
        *(__half2*)(g_Qh + (size_t)r0*DD + c) = __floats2half2_rn(v0,v1);
        *(__half2*)(g_Qh + (size_t)r1*DD + c) = __floats2half2_rn(v2,v3);
      } else if (sec == 1){
        *(__half2*)(g_Kh + (size_t)r0*DD + c) = __floats2half2_rn(v0,v1);
        *(__half2*)(g_Kh + (size_t)r1*DD + c) = __floats2half2_rn(v2,v3);
      } else {
        // V transposed: VT[b][d][l]; r is global row b*L+l, d = c
        int b0=r0>>11, m0=r0&2047, b1=r1>>11, m1=r1&2047;
        __half* VT0 = g_VTh + (size_t)b0*DD*LL;
        __half* VT1 = g_VTh + (size_t)b1*DD*LL;
        VT0[(size_t)(c  )*LL + m0] = __float2half_rn(v0);
        VT0[(size_t)(c+1)*LL + m0] = __float2half_rn(v1);
        VT1[(size_t)(c  )*LL + m1] = __float2half_rn(v2);
        VT1[(size_t)(c+1)*LL + m1] = __float2half_rn(v3);
      }
    }
  }
}

// ============================================================
// P-GEMM fp16: P = exp(Q K^T / 16) -> g_Ph (fp16) + fused colsum.
// CTA 128x128, BK=64 (4 kt iters), 128 threads, 4 warps of 64x64.
// smem: row = 32 half2 + 4 pad = 36 u32. Stage (A or B) = 128*36 u32.
// A stages at 0, 4608; B at 9216, 13824. Total 73728 B.
// ============================================================
__global__ __launch_bounds__(128,2) void pexp_gemm(__half* __restrict__ Pout)
{
  extern __shared__ uint32_t sm[];
  const int z = blockIdx.z;
  const __half* A = g_Qh + (size_t)z*LL*DD;
  const __half* B = g_Kh + (size_t)z*LL*DD;
  __half* C = Pout + (size_t)z*LL*LL;

  const int bm0 = blockIdx.y * 128;
  const int bn0 = blockIdx.x * 128;
  const int tid = threadIdx.x;
  const int warp = tid >> 5, lane = tid & 31;
  const int g = lane >> 2, t = lane & 3;
  const int wm0 = (warp >> 1) * 64;
  const int wn0 = (warp & 1) * 64;
  const uint32_t sb = (uint32_t)__cvta_generic_to_shared(sm);
  const int lr = tid >> 3;            // 0..15
  const int ch = tid & 7;             // 16B chunk (8 halves)

  float acc[4][8][4];
  #pragma unroll
  for (int i=0;i<4;i++)
    #pragma unroll
    for (int j=0;j<8;j++)
      #pragma unroll
      for (int f=0;f<4;f++) acc[i][j][f]=0.f;

  #define P_LOAD(kt, stg) { \
    _Pragma("unroll") \
    for (int i=0;i<8;i++){ \
      int r = lr + i*16; \
      cp16(sb + (((stg)*4608 + r*36 + ch*4)<<2), A + (size_t)(bm0+r)*DD + (kt)*64 + ch*8); \
    } \
    _Pragma("unroll") \
    for (int i=0;i<8;i++){ \
      int r = lr + i*16; \
      cp16(sb + ((9216 + (stg)*4608 + r*36 + ch*4)<<2), B + (size_t)(bn0+r)*DD + (kt)*64 + ch*8); \
    } \
  }

  P_LOAD(0,0); cpcommit();
  for (int kt = 0; kt < 4; kt++){
    const int stg = kt & 1;
    if (kt+1 < 4){ P_LOAD(kt+1, stg^1); cpcommit(); cpwait<1>(); }
    else cpwait<0>();
    __syncthreads();

    const uint32_t* As_ = sm + stg*4608;
    const uint32_t* Bs_ = sm + 9216 + stg*4608;
    #pragma unroll
    for (int ks=0; ks<4; ks++){
      const int k0 = ks*8;             // half2 units
      uint32_t af[4][4], bf[8][2];
      #pragma unroll
      for (int mi=0;mi<4;mi++){
        int r = wm0 + mi*16;
        af[mi][0]=As_[(r+g  )*36 + k0 + t];
        af[mi][1]=As_[(r+g+8)*36 + k0 + t];
        af[mi][2]=As_[(r+g  )*36 + k0 + t+4];
        af[mi][3]=As_[(r+g+8)*36 + k0 + t+4];
      }
      #pragma unroll
      for (int ni=0;ni<8;ni++){
        int c = wn0 + ni*8;
        bf[ni][0]=Bs_[(c+g)*36 + k0 + t];
        bf[ni][1]=Bs_[(c+g)*36 + k0 + t+4];
      }
      #pragma unroll
      for (int mi=0;mi<4;mi++)
        #pragma unroll
        for (int ni=0;ni<8;ni++)
          MMAH(af[mi][0],af[mi][1],af[mi][2],af[mi][3],bf[ni][0],bf[ni][1],acc[mi][ni]);
    }
    __syncthreads();
  }
  #undef P_LOAD

  float csum[8][2];
  #pragma unroll
  for (int ni=0;ni<8;ni++){ csum[ni][0]=0.f; csum[ni][1]=0.f; }

  #pragma unroll
  for (int mi=0;mi<4;mi++){
    #pragma unroll
    for (int ni=0;ni<8;ni++){
      int r0 = bm0 + wm0 + mi*16 + g;
      int c  = bn0 + wn0 + ni*8 + 2*t;
      float e0=__expf(acc[mi][ni][0]*0.0625f), e1=__expf(acc[mi][ni][1]*0.0625f);
      float e2=__expf(acc[mi][ni][2]*0.0625f), e3=__expf(acc[mi][ni][3]*0.0625f);
      *(__half2*)(C + (size_t)r0*LL + c)     = __floats2half2_rn(e0,e1);
      *(__half2*)(C + (size_t)(r0+8)*LL + c) = __floats2half2_rn(e2,e3);
      csum[ni][0] += e0+e2; csum[ni][1] += e1+e3;
    }
  }
  float* sCol = (float*)sm;
  __syncthreads();
  sCol[tid] = 0.f;
  __syncthreads();
  #pragma unroll
  for (int ni=0;ni<8;ni++){
    atomicAdd(&sCol[wn0 + ni*8 + 2*t    ], csum[ni][0]);
    atomicAdd(&sCol[wn0 + ni*8 + 2*t + 1], csum[ni][1]);
  }
  __syncthreads();
  atomicAdd(&g_colsum[z*LL + bn0 + tid], sCol[tid]);
}

// ============================================================
// AV GEMM fp16: A_out = P/colsum (fp32, written once), C = A_out @ V.
// BM=64, BN=256, BK=64 (32 kt iters), 128 threads, 4 warps of 64x64.
// A: LDG fp16 P + fp32 normalize + STG A + half2(x64) smem.
// B: cp.async of g_VTh [d][l].
// smem u32: As 2*2304, Bs 2*9216 -> 23040 u32 = 92160 B
// ============================================================
__global__ __launch_bounds__(128,2) void gemm_av(
    const __half* __restrict__ P, float* __restrict__ Aout,
    float* __restrict__ Cg)
{
  extern __shared__ uint32_t sm[];
  const int z = blockIdx.z;
  const __half* Pz = P + (size_t)z*LL*LL;
  float* Az = Aout + (size_t)z*LL*LL;
  const __half* B = g_VTh + (size_t)z*DD*LL;
  float* C = Cg + (size_t)z*(2LL*LL*DD);
  const float* inv = g_colsum + z*LL;

  const int bm0 = blockIdx.y * 64;
  const int tid = threadIdx.x;
  const int warp = tid >> 5, lane = tid & 31;
  const int g = lane >> 2, t = lane & 3;
  const int wn0 = warp * 64;
  const uint32_t sb = (uint32_t)__cvta_generic_to_shared(sm);
  const int ar = tid >> 3;      // 0..15
  const int ch = tid & 7;       // 8-half chunk

  float acc[4][8][4];
  #pragma unroll
  for (int i=0;i<4;i++)
    #pragma unroll
    for (int j=0;j<8;j++)
      #pragma unroll
      for (int f=0;f<4;f++) acc[i][j][f]=0.f;

  uint32_t areg[16];   // 4 rows x 4 half2

  // normalize + emit: reads P fp16, writes A fp32, builds x64 fp16 regs
  #define PROC_A(kt) { \
    float4 iva = *(const float4*)(inv + (kt)*64 + ch*8); \
    float4 ivb = *(const float4*)(inv + (kt)*64 + ch*8 + 4); \
    _Pragma("unroll") \
    for (int i=0;i<4;i++){ \
      int row = bm0 + ar + i*16; \
      uint4 pr = *(const uint4*)(Pz + (size_t)row*LL + (kt)*64 + ch*8); \
      float2 f0=__half22float2(u2h(pr.x)), f1=__half22float2(u2h(pr.y)); \
      float2 f2=__half22float2(u2h(pr.z)), f3=__half22float2(u2h(pr.w)); \
      f0.x*=iva.x; f0.y*=iva.y; f1.x*=iva.z; f1.y*=iva.w; \
      f2.x*=ivb.x; f2.y*=ivb.y; f3.x*=ivb.z; f3.y*=ivb.w; \
      float* ao = Az + (size_t)row*LL + (kt)*64 + ch*8; \
      *(float4*)ao     = make_float4(f0.x,f0.y,f1.x,f1.y); \
      *(float4*)(ao+4) = make_float4(f2.x,f2.y,f3.x,f3.y); \
      areg[i*4+0]=h2u(__floats2half2_rn(f0.x*64.f, f0.y*64.f)); \
      areg[i*4+1]=h2u(__floats2half2_rn(f1.x*64.f, f1.y*64.f)); \
      areg[i*4+2]=h2u(__floats2half2_rn(f2.x*64.f, f2.y*64.f)); \
      areg[i*4+3]=h2u(__floats2half2_rn(f3.x*64.f, f3.y*64.f)); \
    } \
  }
  #define LOAD_B(kt, stg) { \
    _Pragma("unroll") \
    for (int i=0;i<16;i++){ \
      int d = (tid>>3) + i*16; \
      cp16(sb + ((4608 + (stg)*9216 + d*36 + ch*4)<<2), B + (size_t)d*LL + (kt)*64 + ch*8); \
    } \
  }

  PROC_A(0);
  LOAD_B(0,0); cpcommit();

  const int nk = LL/64;   // 32
  for (int kt = 0; kt < nk; kt++){
    const int stg = kt & 1;
    // store processed A tile kt to smem
    #pragma unroll
    for (int i=0;i<4;i++){
      uint32_t* d = sm + stg*2304 + (ar + i*16)*36 + ch*4;
      *(uint4*)d = make_uint4(areg[i*4],areg[i*4+1],areg[i*4+2],areg[i*4+3]);
    }
    const bool more = (kt + 1 < nk);
    uint4 rawp[4]; float4 iva, ivb;
    if (more){
      LOAD_B(kt+1, stg^1); cpcommit();
      iva = *(const float4*)(inv + (kt+1)*64 + ch*8);
      ivb = *(const float4*)(inv + (kt+1)*64 + ch*8 + 4);
      #pragma unroll
      for (int i=0;i<4;i++)
        rawp[i] = *(const uint4*)(Pz + (size_t)(bm0 + ar + i*16)*LL + (kt+1)*64 + ch*8);
      cpwait<1>();
    } else {
      cpwait<0>();
    }
    __syncthreads();

    const uint32_t* As_ = sm + stg*2304;
    const uint32_t* Bs_ = sm + 4608 + stg*9216;
    #pragma unroll
    for (int ks=0; ks<4; ks++){
      const int k0 = ks*8;
      uint32_t af[4][4], bf[8][2];
      #pragma unroll
      for (int mi=0;mi<4;mi++){
        int r = mi*16;
        af[mi][0]=As_[(r+g  )*36 + k0 + t];
        af[mi][1]=As_[(r+g+8)*36 + k0 + t];
        af[mi][2]=As_[(r+g  )*36 + k0 + t+4];
        af[mi][3]=As_[(r+g+8)*36 + k0 + t+4];
      }
      #pragma unroll
      for (int ni=0;ni<8;ni++){
        int c = wn0 + ni*8;
        bf[ni][0]=Bs_[(c+g)*36 + k0 + t];
        bf[ni][1]=Bs_[(c+g)*36 + k0 + t+4];
      }
      #pragma unroll
      for (int mi=0;mi<4;mi++)
        #pragma unroll
        for (int ni=0;ni<8;ni++)
          MMAH(af[mi][0],af[mi][1],af[mi][2],af[mi][3],bf[ni][0],bf[ni][1],acc[mi][ni]);
    }

    if (more){
      #pragma unroll
      for (int i=0;i<4;i++){
        int row = bm0 + ar + i*16;
        float2 f0=__half22float2(u2h(rawp[i].x)), f1=__half22float2(u2h(rawp[i].y));
        float2 f2=__half22float2(u2h(rawp[i].z)), f3=__half22float2(u2h(rawp[i].w));
        f0.x*=iva.x; f0.y*=iva.y; f1.x*=iva.z; f1.y*=iva.w;
        f2.x*=ivb.x; f2.y*=ivb.y; f3.x*=ivb.z; f3.y*=ivb.w;
        float* ao = Az + (size_t)row*LL + (kt+1)*64 + ch*8;
        *(float4*)ao     = make_float4(f0.x,f0.y,f1.x,f1.y);
        *(float4*)(ao+4) = make_float4(f2.x,f2.y,f3.x,f3.y);
        areg[i*4+0]=h2u(__floats2half2_rn(f0.x*64.f, f0.y*64.f));
        areg[i*4+1]=h2u(__floats2half2_rn(f1.x*64.f, f1.y*64.f));
        areg[i*4+2]=h2u(__floats2half2_rn(f2.x*64.f, f2.y*64.f));
        areg[i*4+3]=h2u(__floats2half2_rn(f3.x*64.f, f3.y*64.f));
      }
    }
    __syncthreads();
  }
  #undef PROC_A
  #undef LOAD_B

  const float s = 0.015625f;  // 1/64
  #pragma unroll
  for (int mi=0;mi<4;mi++){
    #pragma unroll
    for (int ni=0;ni<8;ni++){
      int r = bm0 + mi*16 + g;
      int c = wn0 + ni*8 + 2*t;
      *(float2*)(C + (size_t)r*DD + c)     = make_float2(acc[mi][ni][0]*s,acc[mi][ni][1]*s);
      *(float2*)(C + (size_t)(r+8)*DD + c) = make_float2(acc[mi][ni][2]*s,acc[mi][ni][3]*s);
    }
  }
}

// ============================================================
extern "C" void kernel_launch(void* const* d_in, const int* in_sizes, int n_in,
                              void* d_out, int out_size)
{
  const float* x  = (const float*)d_in[0];
  const float* Wq = (const float*)d_in[1];
  const float* bq = (const float*)d_in[2];
  const float* Wk = (const float*)d_in[3];
  const float* bk = (const float*)d_in[4];
  const float* Wv = (const float*)d_in[5];
  const float* bv = (const float*)d_in[6];

  float* sp   = (float*)d_out;                  // S_p [B, 2L, D]
  float* Aout = sp + (size_t)BB*2*LL*DD;        // A   [B, L, L]

  __half* gPh;
  cudaGetSymbolAddress((void**)&gPh, g_Ph);

  const int SMQKV = 73728, SMP = 73728, SMAV = 92160;
  cudaFuncSetAttribute(qkv_gemm,  cudaFuncAttributeMaxDynamicSharedMemorySize, SMQKV);
  cudaFuncSetAttribute(pexp_gemm, cudaFuncAttributeMaxDynamicSharedMemorySize, SMP);
  cudaFuncSetAttribute(gemm_av,   cudaFuncAttributeMaxDynamicSharedMemorySize, SMAV);

  zerocs_kernel<<<BB*LL/256, 256>>>();

  // Fused QKV projection (tf32), emits fp16 Q/K/V^T
  qkv_gemm<<<dim3(6,128,1), 128, SMQKV>>>(x, Wq, bq, Wk, bk, Wv, bv, sp);

  // P = exp(Q K^T / 16) -> fp16 scratch + fused column sums
  pexp_gemm<<<dim3(16,16,BB), 128, SMP>>>(gPh);

  invcs_kernel<<<BB*LL/256, 256>>>();

  // A = P/colsum (fp32, written once) and C = A @ V
  gemm_av<<<dim3(1,32,BB), 128, SMAV>>>(gPh, Aout, sp + (size_t)LL*DD);
}